// round 15
// baseline (speedup 1.0000x reference)
#include <cuda_runtime.h>
#include <cuda_fp16.h>
#include <cstdint>

#define N_NODES 50000
#define N_EDGES 800000
#define D 128
#define NUM_GRAPHS 128
#define N_LAYERS 4
#define BN_EPS 1e-5f

#define MT 128
#define GEMM_GRID ((N_NODES + MT - 1) / MT)

#define SCAN_BLK 1024
#define SCAN_NBLK ((N_NODES + SCAN_BLK - 1) / SCAN_BLK)

// ---- smem byte map for gemm_mma (106496 B, 2 CTAs/SM) ----
#define AH_B  2048
#define W1_B  (AH_B + 34816)
#define W2_B  (W1_B + 34816)
#define SM_BYTES (W2_B + 34816)   // 106496
#define SB1F  0
#define SB2F  128
#define SSUMF 256
#define SSQF  384
#define SZST  512                 // Z staging fp32 (spans A+W1), stride 132

// ---------------- device scratch ----------------
__device__ __half g_h16[(size_t)N_NODES * D];
__device__ __half g_a16[(size_t)N_NODES * D];
__device__ int    g_deg[N_NODES];
__device__ int    g_ptr[N_NODES + 1];
__device__ int    g_cursor[N_NODES];
__device__ int    g_csr[N_EDGES];
__device__ int    g_bsum[SCAN_NBLK];
__device__ float  g_stats[(N_LAYERS - 1) * 2 * D];
__device__ int    g_idx64;
__device__ int    g_scan_done;

__device__ __forceinline__ int load_idx(const void* p, int i) {
    if (g_idx64) return (int)((const long long*)p)[i];
    return ((const int*)p)[i];
}

__device__ __forceinline__ uint32_t pack_h2(__half a, __half b) {
    __half2 h = __halves2half2(a, b);
    return *(uint32_t*)&h;
}

__device__ __forceinline__ void mma16(float* c, uint32_t a0, uint32_t a1,
                                      uint32_t a2, uint32_t a3,
                                      uint32_t b0, uint32_t b1) {
    asm volatile(
        "mma.sync.aligned.m16n8k16.row.col.f32.f16.f16.f32 "
        "{%0,%1,%2,%3}, {%4,%5,%6,%7}, {%8,%9}, {%0,%1,%2,%3};"
        : "+f"(c[0]), "+f"(c[1]), "+f"(c[2]), "+f"(c[3])
        : "r"(a0), "r"(a1), "r"(a2), "r"(a3), "r"(b0), "r"(b1));
}

// ---------------- launch 0: detect + zero + x->fp16 ----------------
__global__ void zero_kernel(const void* __restrict__ ei,
                            const float* __restrict__ x,
                            float* __restrict__ out) {
    const int tid = threadIdx.x;
    if (blockIdx.x == 0) {
        __shared__ int snz;
        if (tid == 0) snz = 0;
        __syncthreads();
        int step = (2 * N_EDGES) / 256;
        int pos = (tid * step) | 1;
        if (((const int*)ei)[pos] != 0) snz = 1;
        __syncthreads();
        if (tid == 0) g_idx64 = snz ? 0 : 1;
    }
    int gidx = blockIdx.x * 256 + tid;
    int stride = gridDim.x * 256;
    for (int t = gidx; t < (N_LAYERS - 1) * 2 * D; t += stride) g_stats[t] = 0.0f;
    for (int t = gidx; t < NUM_GRAPHS * D; t += stride) out[t] = 0.0f;
    for (int t = gidx; t < N_NODES * (D / 2); t += stride) {
        float2 v = ((const float2*)x)[t];
        ((__half2*)g_h16)[t] = __floats2half2_rn(v.x, v.y);
    }
}

// ---------------- launch 1: histogram ----------------
__global__ void hist_kernel(const void* __restrict__ ei) {
    int e = blockIdx.x * blockDim.x + threadIdx.x;
    if (e < N_EDGES) {
        int dst = load_idx(ei, N_EDGES + e);
        if (dst >= 0 && dst < N_NODES) atomicAdd(&g_deg[dst], 1);
    }
}

// ---------------- launch 2: full scan in one kernel ----------------
__global__ void scan_all_kernel() {
    __shared__ int wsum[32];
    __shared__ int sticket;
    const int tid = threadIdx.x;
    const int lane = tid & 31, wid = tid >> 5;
    int idx = blockIdx.x * SCAN_BLK + tid;
    int v = (idx < N_NODES) ? g_deg[idx] : 0;
    if (idx < N_NODES) g_deg[idx] = 0;
    int s = v;
    #pragma unroll
    for (int off = 1; off < 32; off <<= 1) {
        int t = __shfl_up_sync(0xffffffffu, s, off);
        if (lane >= off) s += t;
    }
    if (lane == 31) wsum[wid] = s;
    __syncthreads();
    if (wid == 0) {
        int ws = wsum[lane];
        #pragma unroll
        for (int off = 1; off < 32; off <<= 1) {
            int t = __shfl_up_sync(0xffffffffu, ws, off);
            if (lane >= off) ws += t;
        }
        wsum[lane] = ws;
    }
    __syncthreads();
    int incl = s + ((wid > 0) ? wsum[wid - 1] : 0);
    if (idx < N_NODES) g_ptr[idx + 1] = incl;
    if (tid == SCAN_BLK - 1) g_bsum[blockIdx.x] = incl;
    __threadfence();
    __syncthreads();
    if (tid == 0) sticket = atomicAdd(&g_scan_done, 1);
    __syncthreads();

    if (sticket == SCAN_NBLK - 1) {
        __shared__ int carry[SCAN_NBLK];
        if (tid < SCAN_NBLK) carry[tid] = ((volatile int*)g_bsum)[tid];
        __syncthreads();
        if (tid == 0) {
            int run = 0;
            for (int b = 0; b < SCAN_NBLK; b++) {
                int t = carry[b]; carry[b] = run; run += t;
            }
            g_scan_done = 0;
        }
        __syncthreads();
        volatile int* vptr = g_ptr;
        for (int i = tid; i < N_NODES; i += SCAN_BLK) {
            int p = vptr[i + 1] + carry[i / SCAN_BLK];
            g_ptr[i + 1] = p;
            if (i + 1 < N_NODES) g_cursor[i + 1] = p;
        }
        if (tid == 0) { g_ptr[0] = 0; g_cursor[0] = 0; }
    }
}

// ---------------- launch 3: CSR fill ----------------
__global__ void fill_kernel(const void* __restrict__ ei) {
    int e = blockIdx.x * blockDim.x + threadIdx.x;
    if (e >= N_EDGES) return;
    int src = load_idx(ei, e);
    int dst = load_idx(ei, N_EDGES + e);
    if (dst < 0 || dst >= N_NODES || src < 0 || src >= N_NODES) return;
    int p = atomicAdd(&g_cursor[dst], 1);
    if (p >= 0 && p < N_EDGES) g_csr[p] = src;
}

// ---------------- gather (fp16 src) + fused BN+ReLU  [MLP-8] ----------------
__device__ __forceinline__ float4 ldh4(size_t ridx, int lane) {
    uint2 u = ((const uint2*)g_h16)[ridx * 32 + lane];
    float2 f0 = __half22float2(*(__half2*)&u.x);
    float2 f1 = __half22float2(*(__half2*)&u.y);
    return make_float4(f0.x, f0.y, f1.x, f1.y);
}

__global__ void __launch_bounds__(256) gather_kernel(
    const float* __restrict__ eps_arr,
    const float* __restrict__ gamma, const float* __restrict__ beta,
    int layer)
{
    __shared__ float ssc[D], ssh[D];
    const int tid = threadIdx.x;
    const int apply_bn = (layer > 0);
    if (apply_bn && tid < D) {
        const float* stats = &g_stats[(layer - 1) * 2 * D];
        const float invN = 1.0f / (float)N_NODES;
        float mu = stats[tid] * invN;
        float var = stats[D + tid] * invN - mu * mu;
        float sc = rsqrtf(var + BN_EPS) * gamma[tid];
        ssc[tid] = sc;
        ssh[tid] = beta[tid] - mu * sc;
    }
    __syncthreads();

    const int lane = tid & 31, wid = tid >> 5;
    const int r = blockIdx.x * 8 + wid;
    if (r >= N_NODES) return;

    float4 sc4 = make_float4(1.f, 1.f, 1.f, 1.f);
    float4 sh4 = make_float4(0.f, 0.f, 0.f, 0.f);
    if (apply_bn) {
        sc4 = *(const float4*)&ssc[lane * 4];
        sh4 = *(const float4*)&ssh[lane * 4];
    }
    const float ep = 1.0f + eps_arr[layer];

    float4 v = ldh4((size_t)r, lane);
    float4 acc;
    if (apply_bn) {
        acc.x = ep * fmaxf(v.x * sc4.x + sh4.x, 0.0f);
        acc.y = ep * fmaxf(v.y * sc4.y + sh4.y, 0.0f);
        acc.z = ep * fmaxf(v.z * sc4.z + sh4.z, 0.0f);
        acc.w = ep * fmaxf(v.w * sc4.w + sh4.w, 0.0f);
    } else {
        acc.x = ep * v.x; acc.y = ep * v.y; acc.z = ep * v.z; acc.w = ep * v.w;
    }

    const int e0 = g_ptr[r], end = g_ptr[r + 1];
    for (int base = e0; base < end; base += 32) {
        const int cnt = min(end - base, 32);
        int myidx = (lane < cnt) ? g_csr[base + lane] : 0;
        int t0 = 0;
        for (; t0 + 8 <= cnt; t0 += 8) {
            int ss[8];
            #pragma unroll
            for (int t = 0; t < 8; t++) ss[t] = __shfl_sync(0xffffffffu, myidx, t0 + t);
            float4 u[8];
            #pragma unroll
            for (int t = 0; t < 8; t++) u[t] = ldh4((size_t)ss[t], lane);
            #pragma unroll
            for (int t = 0; t < 8; t++) {
                if (apply_bn) {
                    acc.x += fmaxf(u[t].x * sc4.x + sh4.x, 0.0f);
                    acc.y += fmaxf(u[t].y * sc4.y + sh4.y, 0.0f);
                    acc.z += fmaxf(u[t].z * sc4.z + sh4.z, 0.0f);
                    acc.w += fmaxf(u[t].w * sc4.w + sh4.w, 0.0f);
                } else {
                    acc.x += u[t].x; acc.y += u[t].y;
                    acc.z += u[t].z; acc.w += u[t].w;
                }
            }
        }
        for (; t0 < cnt; t0++) {
            int s = __shfl_sync(0xffffffffu, myidx, t0);
            float4 u = ldh4((size_t)s, lane);
            if (apply_bn) {
                acc.x += fmaxf(u.x * sc4.x + sh4.x, 0.0f);
                acc.y += fmaxf(u.y * sc4.y + sh4.y, 0.0f);
                acc.z += fmaxf(u.z * sc4.z + sh4.z, 0.0f);
                acc.w += fmaxf(u.w * sc4.w + sh4.w, 0.0f);
            } else {
                acc.x += u.x; acc.y += u.y; acc.z += u.z; acc.w += u.w;
            }
        }
    }
    uint2 packed;
    packed.x = pack_h2(__float2half_rn(acc.x), __float2half_rn(acc.y));
    packed.y = pack_h2(__float2half_rn(acc.z), __float2half_rn(acc.w));
    ((uint2*)g_a16)[(size_t)r * 32 + lane] = packed;
}

// ---------------- W fill: global [k][n] fp32 -> smem [n][k] fp16 ----------------
__device__ __forceinline__ void fill_w(char* smem, int woff,
                                       const float* __restrict__ Wg,
                                       int wid, int lane) {
    #pragma unroll 1
    for (int s = 0; s < 8; s++) {
        int task = wid + s * 8;
        int k0 = (task >> 2) * 8;
        int n = (task & 3) * 32 + lane;
        float w[8];
        #pragma unroll
        for (int r = 0; r < 8; r++) w[r] = Wg[(size_t)(k0 + r) * 128 + n];
        __half hh[8];
        #pragma unroll
        for (int r = 0; r < 8; r++) hh[r] = __float2half_rn(w[r]);
        uint4 uh;
        uh.x = pack_h2(hh[0], hh[1]); uh.y = pack_h2(hh[2], hh[3]);
        uh.z = pack_h2(hh[4], hh[5]); uh.w = pack_h2(hh[6], hh[7]);
        *(uint4*)(smem + woff + ((size_t)n * 136 + k0) * 2) = uh;
    }
}

// ---------------- one 128x128x128 GEMM (A fp16, W fp16, fp32 acc) ------------
__device__ __forceinline__ void gemm128(const char* __restrict__ smem, int woff,
                                        float (&acc)[4][4][4],
                                        int wr, int wc, int g, int t)
{
    #pragma unroll 1
    for (int ks = 0; ks < 8; ks++) {
        const int k0 = ks * 16;
        uint32_t ah[4][4];
        #pragma unroll
        for (int i = 0; i < 4; i++) {
            int ob = ((wr + i * 16 + g) * 136 + k0 + 2 * t) * 2;
            ah[i][0] = *(const uint32_t*)(smem + AH_B + ob);
            ah[i][1] = *(const uint32_t*)(smem + AH_B + ob + 2176);
            ah[i][2] = *(const uint32_t*)(smem + AH_B + ob + 16);
            ah[i][3] = *(const uint32_t*)(smem + AH_B + ob + 2192);
        }
        #pragma unroll
        for (int j = 0; j < 4; j++) {
            int wb = ((wc + j * 8 + g) * 136 + k0 + 2 * t) * 2;
            uint32_t b0 = *(const uint32_t*)(smem + woff + wb);
            uint32_t b1 = *(const uint32_t*)(smem + woff + wb + 16);
            #pragma unroll
            for (int i = 0; i < 4; i++) {
                mma16(acc[i][j], ah[i][0], ah[i][1], ah[i][2], ah[i][3], b0, b1);
            }
        }
    }
}

// ---------------- GEMM kernel: Z = relu(A@W1+b1)@W2 + b2 + epilogue ----------------
__global__ void __launch_bounds__(256, 2) gemm_mma(
    const float* __restrict__ W1, const float* __restrict__ b1,
    const float* __restrict__ W2, const float* __restrict__ b2,
    int layer, float* __restrict__ out, const void* __restrict__ batch, int last)
{
    extern __shared__ char smem[];
    float* smf = (float*)smem;
    const int tid = threadIdx.x;
    const int wid = tid >> 5, lane = tid & 31;
    const int g = lane >> 2, t = lane & 3;
    const int wr = (wid >> 2) * 64;
    const int wc = (wid & 3) * 32;
    const int r0 = blockIdx.x * MT;

    if (tid < 128) {
        smf[SB1F + tid] = b1[tid];
        smf[SB2F + tid] = b2[tid];
        smf[SSUMF + tid] = 0.0f;
        smf[SSQF + tid] = 0.0f;
    }

    // A fill: fp16 g_a16 -> smem, straight uint4 copies
    #pragma unroll
    for (int it = 0; it < 8; it++) {
        int idx = tid + it * 256;
        int m = idx >> 4, c8 = idx & 15;
        uint4 v = make_uint4(0u, 0u, 0u, 0u);
        if (r0 + m < N_NODES) v = ((const uint4*)g_a16)[(size_t)(r0 + m) * 16 + c8];
        *(uint4*)(smem + AH_B + ((size_t)m * 136 + c8 * 8) * 2) = v;
    }
    // both W fills upfront (off the inter-GEMM critical path)
    fill_w(smem, W1_B, W1, wid, lane);
    fill_w(smem, W2_B, W2, wid, lane);
    __syncthreads();

    float acc[4][4][4];
    #pragma unroll
    for (int i = 0; i < 4; i++)
        #pragma unroll
        for (int j = 0; j < 4; j++)
            #pragma unroll
            for (int c = 0; c < 4; c++) acc[i][j][c] = 0.0f;

    gemm128(smem, W1_B, acc, wr, wc, g, t);
    __syncthreads();

    // T = relu(acc + b1) -> back into A (fp16)
    #pragma unroll
    for (int i = 0; i < 4; i++) {
        #pragma unroll
        for (int j = 0; j < 4; j++) {
            int c0 = wc + j * 8 + 2 * t;
            int rA = wr + i * 16 + g;
            float bb0 = smf[SB1F + c0], bb1 = smf[SB1F + c0 + 1];
            float v00 = fmaxf(acc[i][j][0] + bb0, 0.0f);
            float v01 = fmaxf(acc[i][j][1] + bb1, 0.0f);
            float v10 = fmaxf(acc[i][j][2] + bb0, 0.0f);
            float v11 = fmaxf(acc[i][j][3] + bb1, 0.0f);
            __half2 p0 = __floats2half2_rn(v00, v01);
            __half2 p1 = __floats2half2_rn(v10, v11);
            *(uint32_t*)(smem + AH_B + (rA * 136 + c0) * 2) = *(uint32_t*)&p0;
            *(uint32_t*)(smem + AH_B + ((rA + 8) * 136 + c0) * 2) = *(uint32_t*)&p1;
            acc[i][j][0] = 0.0f; acc[i][j][1] = 0.0f;
            acc[i][j][2] = 0.0f; acc[i][j][3] = 0.0f;
        }
    }
    __syncthreads();

    gemm128(smem, W2_B, acc, wr, wc, g, t);
    __syncthreads();

    // stage z = acc + b2 into fp32 staging (A+W1 regions are dead now)
    #pragma unroll
    for (int i = 0; i < 4; i++) {
        #pragma unroll
        for (int j = 0; j < 4; j++) {
            int c0 = wc + j * 8 + 2 * t;
            int rA = wr + i * 16 + g;
            float bb0 = smf[SB2F + c0], bb1 = smf[SB2F + c0 + 1];
            float2 u0 = make_float2(acc[i][j][0] + bb0, acc[i][j][1] + bb1);
            float2 u1 = make_float2(acc[i][j][2] + bb0, acc[i][j][3] + bb1);
            *(float2*)&smf[SZST + rA * 132 + c0] = u0;
            *(float2*)&smf[SZST + (rA + 8) * 132 + c0] = u1;
        }
    }
    __syncthreads();

    const int col4 = tid & 31;
    if (!last) {
        float s[4] = {0, 0, 0, 0}, q[4] = {0, 0, 0, 0};
        #pragma unroll
        for (int it = 0; it < 16; it++) {
            int row = (tid >> 5) + it * 8;
            int r = r0 + row;
            if (r < N_NODES) {
                float4 z4 = *(const float4*)&smf[SZST + row * 132 + col4 * 4];
                uint2 packed;
                packed.x = pack_h2(__float2half_rn(z4.x), __float2half_rn(z4.y));
                packed.y = pack_h2(__float2half_rn(z4.z), __float2half_rn(z4.w));
                *(uint2*)&g_h16[(size_t)r * D + col4 * 4] = packed;
                s[0] += z4.x; q[0] += z4.x * z4.x;
                s[1] += z4.y; q[1] += z4.y * z4.y;
                s[2] += z4.z; q[2] += z4.z * z4.z;
                s[3] += z4.w; q[3] += z4.w * z4.w;
            }
        }
        #pragma unroll
        for (int j = 0; j < 4; j++) {
            atomicAdd(&smf[SSUMF + col4 * 4 + j], s[j]);
            atomicAdd(&smf[SSQF + col4 * 4 + j], q[j]);
        }
        __syncthreads();
        if (tid < 128) {
            atomicAdd(&g_stats[layer * 2 * D + tid], smf[SSUMF + tid]);
            atomicAdd(&g_stats[layer * 2 * D + D + tid], smf[SSQF + tid]);
        }
    } else {
        int gcur = -1;
        float a0 = 0, a1 = 0, a2 = 0, a3 = 0;
        #pragma unroll 1
        for (int it = 0; it < 16; it++) {
            int row = (tid >> 5) + it * 8;
            int r = r0 + row;
            if (r < N_NODES) {
                float4 z4 = *(const float4*)&smf[SZST + row * 132 + col4 * 4];
                int gg = load_idx(batch, r);
                if (gg == gcur) {
                    a0 += z4.x; a1 += z4.y; a2 += z4.z; a3 += z4.w;
                } else {
                    if (gcur >= 0 && gcur < NUM_GRAPHS) {
                        atomicAdd(&out[gcur * D + col4 * 4 + 0], a0);
                        atomicAdd(&out[gcur * D + col4 * 4 + 1], a1);
                        atomicAdd(&out[gcur * D + col4 * 4 + 2], a2);
                        atomicAdd(&out[gcur * D + col4 * 4 + 3], a3);
                    }
                    gcur = gg; a0 = z4.x; a1 = z4.y; a2 = z4.z; a3 = z4.w;
                }
            }
        }
        if (gcur >= 0 && gcur < NUM_GRAPHS) {
            atomicAdd(&out[gcur * D + col4 * 4 + 0], a0);
            atomicAdd(&out[gcur * D + col4 * 4 + 1], a1);
            atomicAdd(&out[gcur * D + col4 * 4 + 2], a2);
            atomicAdd(&out[gcur * D + col4 * 4 + 3], a3);
        }
    }
}

// ---------------- launch ----------------
extern "C" void kernel_launch(void* const* d_in, const int* in_sizes, int n_in,
                              void* d_out, int out_size) {
    const float* x     = (const float*)d_in[0];
    const void*  ei    = d_in[1];
    const void*  batch = d_in[2];
    const float* W1    = (const float*)d_in[3];
    const float* b1    = (const float*)d_in[4];
    const float* W2    = (const float*)d_in[5];
    const float* b2    = (const float*)d_in[6];
    const float* eps   = (const float*)d_in[7];
    const float* gamma = (const float*)d_in[8];
    const float* beta  = (const float*)d_in[9];
    float* out = (float*)d_out;

    cudaFuncSetAttribute(gemm_mma, cudaFuncAttributeMaxDynamicSharedMemorySize,
                         SM_BYTES);

    zero_kernel<<<128, 256>>>(ei, x, out);                          // 0
    hist_kernel<<<(N_EDGES + 255) / 256, 256>>>(ei);                // 1
    scan_all_kernel<<<SCAN_NBLK, SCAN_BLK>>>();                     // 2
    fill_kernel<<<(N_EDGES + 255) / 256, 256>>>(ei);                // 3

    for (int i = 0; i < N_LAYERS; i++) {
        gather_kernel<<<(N_NODES + 7) / 8, 256>>>(                  // 4 on first iter
            eps, gamma + (i > 0 ? (i - 1) * D : 0),
            beta + (i > 0 ? (i - 1) * D : 0), i);
        gemm_mma<<<GEMM_GRID, 256, SM_BYTES>>>(                     // 5 on first iter
            W1 + i * D * D, b1 + i * D, W2 + i * D * D, b2 + i * D,
            i, out, batch, (i == N_LAYERS - 1) ? 1 : 0);
    }
}

// round 16
// speedup vs baseline: 1.0800x; 1.0800x over previous
#include <cuda_runtime.h>
#include <cuda_fp16.h>
#include <cstdint>

#define N_NODES 50000
#define N_EDGES 800000
#define D 128
#define NUM_GRAPHS 128
#define N_LAYERS 4
#define BN_EPS 1e-5f

#define MT 128
#define GEMM_GRID ((N_NODES + MT - 1) / MT)

#define SCAN_BLK 1024
#define SCAN_NBLK ((N_NODES + SCAN_BLK - 1) / SCAN_BLK)

// ---- smem byte map for gemm_mma (71680 B, 2 CTAs/SM) ----
#define AH_B 2048
#define WF_B (AH_B + 34816)
#define SM_BYTES (WF_B + 34816)   // 71680
#define SB1F  0
#define SB2F  128
#define SSUMF 256
#define SSQF  384
#define SZST  512                 // Z staging fp32 (spans A+W regions), stride 132

// ---------------- device scratch ----------------
__device__ __half g_h16[(size_t)N_NODES * D];
__device__ __half g_a16[(size_t)N_NODES * D];
__device__ int    g_deg[N_NODES];
__device__ int    g_ptr[N_NODES + 1];
__device__ int    g_cursor[N_NODES];
__device__ int    g_csr[N_EDGES];
__device__ int    g_bsum[SCAN_NBLK];
__device__ float  g_stats[(N_LAYERS - 1) * 2 * D];
__device__ int    g_idx64;
__device__ int    g_scan_done;

__device__ __forceinline__ int load_idx(const void* p, int i) {
    if (g_idx64) return (int)((const long long*)p)[i];
    return ((const int*)p)[i];
}

__device__ __forceinline__ uint32_t pack_h2(__half a, __half b) {
    __half2 h = __halves2half2(a, b);
    return *(uint32_t*)&h;
}

__device__ __forceinline__ void mma16(float* c, uint32_t a0, uint32_t a1,
                                      uint32_t a2, uint32_t a3,
                                      uint32_t b0, uint32_t b1) {
    asm volatile(
        "mma.sync.aligned.m16n8k16.row.col.f32.f16.f16.f32 "
        "{%0,%1,%2,%3}, {%4,%5,%6,%7}, {%8,%9}, {%0,%1,%2,%3};"
        : "+f"(c[0]), "+f"(c[1]), "+f"(c[2]), "+f"(c[3])
        : "r"(a0), "r"(a1), "r"(a2), "r"(a3), "r"(b0), "r"(b1));
}

// ---------------- launch 0: self-detect + hist + zero + x->fp16 ----------------
__global__ void zero_hist_kernel(const void* __restrict__ ei,
                                 const float* __restrict__ x,
                                 float* __restrict__ out) {
    __shared__ int snz;
    const int tid = threadIdx.x;
    if (tid == 0) snz = 0;
    __syncthreads();
    {
        int step = (2 * N_EDGES) / 256;
        int pos = (tid * step) | 1;
        if (((const int*)ei)[pos] != 0) snz = 1;
    }
    __syncthreads();
    const int idx64 = snz ? 0 : 1;

    int gidx = blockIdx.x * 256 + tid;
    if (gidx == 0) g_idx64 = idx64;

    if (gidx < N_EDGES) {
        int dst = idx64 ? (int)((const long long*)ei)[N_EDGES + gidx]
                        : ((const int*)ei)[N_EDGES + gidx];
        if (dst >= 0 && dst < N_NODES) atomicAdd(&g_deg[dst], 1);
    }

    int stride = gridDim.x * 256;
    for (int t = gidx; t < (N_LAYERS - 1) * 2 * D; t += stride) g_stats[t] = 0.0f;
    for (int t = gidx; t < NUM_GRAPHS * D; t += stride) out[t] = 0.0f;
    for (int t = gidx; t < N_NODES * (D / 2); t += stride) {
        float2 v = ((const float2*)x)[t];
        ((__half2*)g_h16)[t] = __floats2half2_rn(v.x, v.y);
    }
}

// ---------------- launch 1: full scan in one kernel ----------------
__global__ void scan_all_kernel() {
    __shared__ int wsum[32];
    __shared__ int sticket;
    const int tid = threadIdx.x;
    const int lane = tid & 31, wid = tid >> 5;
    int idx = blockIdx.x * SCAN_BLK + tid;
    int v = (idx < N_NODES) ? g_deg[idx] : 0;
    if (idx < N_NODES) g_deg[idx] = 0;
    int s = v;
    #pragma unroll
    for (int off = 1; off < 32; off <<= 1) {
        int t = __shfl_up_sync(0xffffffffu, s, off);
        if (lane >= off) s += t;
    }
    if (lane == 31) wsum[wid] = s;
    __syncthreads();
    if (wid == 0) {
        int ws = wsum[lane];
        #pragma unroll
        for (int off = 1; off < 32; off <<= 1) {
            int t = __shfl_up_sync(0xffffffffu, ws, off);
            if (lane >= off) ws += t;
        }
        wsum[lane] = ws;
    }
    __syncthreads();
    int incl = s + ((wid > 0) ? wsum[wid - 1] : 0);
    if (idx < N_NODES) g_ptr[idx + 1] = incl;
    if (tid == SCAN_BLK - 1) g_bsum[blockIdx.x] = incl;
    __threadfence();
    __syncthreads();
    if (tid == 0) sticket = atomicAdd(&g_scan_done, 1);
    __syncthreads();

    if (sticket == SCAN_NBLK - 1) {
        __shared__ int carry[SCAN_NBLK];
        if (tid < SCAN_NBLK) carry[tid] = ((volatile int*)g_bsum)[tid];
        __syncthreads();
        if (tid == 0) {
            int run = 0;
            for (int b = 0; b < SCAN_NBLK; b++) {
                int t = carry[b]; carry[b] = run; run += t;
            }
            g_scan_done = 0;
        }
        __syncthreads();
        volatile int* vptr = g_ptr;
        for (int i = tid; i < N_NODES; i += SCAN_BLK) {
            int p = vptr[i + 1] + carry[i / SCAN_BLK];
            g_ptr[i + 1] = p;
            if (i + 1 < N_NODES) g_cursor[i + 1] = p;
        }
        if (tid == 0) { g_ptr[0] = 0; g_cursor[0] = 0; }
    }
}

// ---------------- launch 2: CSR fill ----------------
__global__ void fill_kernel(const void* __restrict__ ei) {
    int e = blockIdx.x * blockDim.x + threadIdx.x;
    if (e >= N_EDGES) return;
    int src = load_idx(ei, e);
    int dst = load_idx(ei, N_EDGES + e);
    if (dst < 0 || dst >= N_NODES || src < 0 || src >= N_NODES) return;
    int p = atomicAdd(&g_cursor[dst], 1);
    if (p >= 0 && p < N_EDGES) g_csr[p] = src;
}

// ---------------- gather (fp16 src) + fused BN+ReLU via HFMA2_relu ----------------
__global__ void __launch_bounds__(256) gather_kernel(
    const float* __restrict__ eps_arr,
    const float* __restrict__ gamma, const float* __restrict__ beta,
    int layer)
{
    __shared__ float ssc[D], ssh[D];
    const int tid = threadIdx.x;
    const int apply_bn = (layer > 0);
    if (apply_bn && tid < D) {
        const float* stats = &g_stats[(layer - 1) * 2 * D];
        const float invN = 1.0f / (float)N_NODES;
        float mu = stats[tid] * invN;
        float var = stats[D + tid] * invN - mu * mu;
        float sc = rsqrtf(var + BN_EPS) * gamma[tid];
        ssc[tid] = sc;
        ssh[tid] = beta[tid] - mu * sc;
    }
    __syncthreads();

    const int lane = tid & 31, wid = tid >> 5;
    const int r = blockIdx.x * 8 + wid;
    if (r >= N_NODES) return;

    float4 sc4 = make_float4(1.f, 1.f, 1.f, 1.f);
    float4 sh4 = make_float4(0.f, 0.f, 0.f, 0.f);
    __half2 sc2a, sc2b, sh2a, sh2b;
    if (apply_bn) {
        sc4 = *(const float4*)&ssc[lane * 4];
        sh4 = *(const float4*)&ssh[lane * 4];
        sc2a = __floats2half2_rn(sc4.x, sc4.y);
        sc2b = __floats2half2_rn(sc4.z, sc4.w);
        sh2a = __floats2half2_rn(sh4.x, sh4.y);
        sh2b = __floats2half2_rn(sh4.z, sh4.w);
    }
    const float ep = 1.0f + eps_arr[layer];
    const uint2* __restrict__ h2p = (const uint2*)g_h16;

    // self term in fp32 (once per row)
    float4 acc;
    {
        uint2 u = h2p[(size_t)r * 32 + lane];
        float2 f0 = __half22float2(*(__half2*)&u.x);
        float2 f1 = __half22float2(*(__half2*)&u.y);
        if (apply_bn) {
            acc.x = ep * fmaxf(f0.x * sc4.x + sh4.x, 0.0f);
            acc.y = ep * fmaxf(f0.y * sc4.y + sh4.y, 0.0f);
            acc.z = ep * fmaxf(f1.x * sc4.z + sh4.z, 0.0f);
            acc.w = ep * fmaxf(f1.y * sc4.w + sh4.w, 0.0f);
        } else {
            acc.x = ep * f0.x; acc.y = ep * f0.y;
            acc.z = ep * f1.x; acc.w = ep * f1.y;
        }
    }

    const int e0 = g_ptr[r], end = g_ptr[r + 1];
    if (apply_bn) {
        for (int base = e0; base < end; base += 32) {
            const int cnt = min(end - base, 32);
            int myidx = (lane < cnt) ? g_csr[base + lane] : 0;
            int t0 = 0;
            for (; t0 + 8 <= cnt; t0 += 8) {
                int ss[8];
                #pragma unroll
                for (int t = 0; t < 8; t++)
                    ss[t] = __shfl_sync(0xffffffffu, myidx, t0 + t);
                uint2 u[8];
                #pragma unroll
                for (int t = 0; t < 8; t++)
                    u[t] = h2p[(size_t)ss[t] * 32 + lane];
                #pragma unroll
                for (int t = 0; t < 8; t++) {
                    __half2 a0 = __hfma2_relu(*(__half2*)&u[t].x, sc2a, sh2a);
                    __half2 a1 = __hfma2_relu(*(__half2*)&u[t].y, sc2b, sh2b);
                    float2 f0 = __half22float2(a0);
                    float2 f1 = __half22float2(a1);
                    acc.x += f0.x; acc.y += f0.y;
                    acc.z += f1.x; acc.w += f1.y;
                }
            }
            for (; t0 < cnt; t0++) {
                int s = __shfl_sync(0xffffffffu, myidx, t0);
                uint2 u = h2p[(size_t)s * 32 + lane];
                __half2 a0 = __hfma2_relu(*(__half2*)&u.x, sc2a, sh2a);
                __half2 a1 = __hfma2_relu(*(__half2*)&u.y, sc2b, sh2b);
                float2 f0 = __half22float2(a0);
                float2 f1 = __half22float2(a1);
                acc.x += f0.x; acc.y += f0.y;
                acc.z += f1.x; acc.w += f1.y;
            }
        }
    } else {
        for (int base = e0; base < end; base += 32) {
            const int cnt = min(end - base, 32);
            int myidx = (lane < cnt) ? g_csr[base + lane] : 0;
            int t0 = 0;
            for (; t0 + 8 <= cnt; t0 += 8) {
                int ss[8];
                #pragma unroll
                for (int t = 0; t < 8; t++)
                    ss[t] = __shfl_sync(0xffffffffu, myidx, t0 + t);
                uint2 u[8];
                #pragma unroll
                for (int t = 0; t < 8; t++)
                    u[t] = h2p[(size_t)ss[t] * 32 + lane];
                #pragma unroll
                for (int t = 0; t < 8; t++) {
                    float2 f0 = __half22float2(*(__half2*)&u[t].x);
                    float2 f1 = __half22float2(*(__half2*)&u[t].y);
                    acc.x += f0.x; acc.y += f0.y;
                    acc.z += f1.x; acc.w += f1.y;
                }
            }
            for (; t0 < cnt; t0++) {
                int s = __shfl_sync(0xffffffffu, myidx, t0);
                uint2 u = h2p[(size_t)s * 32 + lane];
                float2 f0 = __half22float2(*(__half2*)&u.x);
                float2 f1 = __half22float2(*(__half2*)&u.y);
                acc.x += f0.x; acc.y += f0.y;
                acc.z += f1.x; acc.w += f1.y;
            }
        }
    }
    uint2 packed;
    packed.x = pack_h2(__float2half_rn(acc.x), __float2half_rn(acc.y));
    packed.y = pack_h2(__float2half_rn(acc.z), __float2half_rn(acc.w));
    ((uint2*)g_a16)[(size_t)r * 32 + lane] = packed;
}

// ---------------- W fill: global [k][n] fp32 -> smem [n][k] fp16 ----------------
__device__ __forceinline__ void fill_w(char* smem, const float* __restrict__ Wg,
                                       int wid, int lane) {
    #pragma unroll 1
    for (int s = 0; s < 8; s++) {
        int task = wid + s * 8;
        int k0 = (task >> 2) * 8;
        int n = (task & 3) * 32 + lane;
        float w[8];
        #pragma unroll
        for (int r = 0; r < 8; r++) w[r] = Wg[(size_t)(k0 + r) * 128 + n];
        __half hh[8];
        #pragma unroll
        for (int r = 0; r < 8; r++) hh[r] = __float2half_rn(w[r]);
        uint4 uh;
        uh.x = pack_h2(hh[0], hh[1]); uh.y = pack_h2(hh[2], hh[3]);
        uh.z = pack_h2(hh[4], hh[5]); uh.w = pack_h2(hh[6], hh[7]);
        *(uint4*)(smem + WF_B + ((size_t)n * 136 + k0) * 2) = uh;
    }
}

// ---------------- one 128x128x128 GEMM (A fp16, W fp16, fp32 acc) ------------
__device__ __forceinline__ void gemm128(const char* __restrict__ smem,
                                        float (&acc)[4][4][4],
                                        int wr, int wc, int g, int t)
{
    #pragma unroll 1
    for (int ks = 0; ks < 8; ks++) {
        const int k0 = ks * 16;
        uint32_t ah[4][4];
        #pragma unroll
        for (int i = 0; i < 4; i++) {
            int ob = ((wr + i * 16 + g) * 136 + k0 + 2 * t) * 2;
            ah[i][0] = *(const uint32_t*)(smem + AH_B + ob);
            ah[i][1] = *(const uint32_t*)(smem + AH_B + ob + 2176);
            ah[i][2] = *(const uint32_t*)(smem + AH_B + ob + 16);
            ah[i][3] = *(const uint32_t*)(smem + AH_B + ob + 2192);
        }
        #pragma unroll
        for (int j = 0; j < 4; j++) {
            int wb = ((wc + j * 8 + g) * 136 + k0 + 2 * t) * 2;
            uint32_t b0 = *(const uint32_t*)(smem + WF_B + wb);
            uint32_t b1 = *(const uint32_t*)(smem + WF_B + wb + 16);
            #pragma unroll
            for (int i = 0; i < 4; i++) {
                mma16(acc[i][j], ah[i][0], ah[i][1], ah[i][2], ah[i][3], b0, b1);
            }
        }
    }
}

// ---------------- GEMM kernel: Z = relu(A@W1+b1)@W2 + b2 + epilogue ----------------
__global__ void __launch_bounds__(256, 2) gemm_mma(
    const float* __restrict__ W1, const float* __restrict__ b1,
    const float* __restrict__ W2, const float* __restrict__ b2,
    int layer, float* __restrict__ out, const void* __restrict__ batch, int last)
{
    extern __shared__ char smem[];
    float* smf = (float*)smem;
    const int tid = threadIdx.x;
    const int wid = tid >> 5, lane = tid & 31;
    const int g = lane >> 2, t = lane & 3;
    const int wr = (wid >> 2) * 64;
    const int wc = (wid & 3) * 32;
    const int r0 = blockIdx.x * MT;

    if (tid < 128) {
        smf[SB1F + tid] = b1[tid];
        smf[SB2F + tid] = b2[tid];
        smf[SSUMF + tid] = 0.0f;
        smf[SSQF + tid] = 0.0f;
    }

    // A fill: fp16 g_a16 -> smem, straight uint4 copies
    #pragma unroll
    for (int it = 0; it < 8; it++) {
        int idx = tid + it * 256;
        int m = idx >> 4, c8 = idx & 15;
        uint4 v = make_uint4(0u, 0u, 0u, 0u);
        if (r0 + m < N_NODES) v = ((const uint4*)g_a16)[(size_t)(r0 + m) * 16 + c8];
        *(uint4*)(smem + AH_B + ((size_t)m * 136 + c8 * 8) * 2) = v;
    }
    fill_w(smem, W1, wid, lane);
    __syncthreads();

    float acc[4][4][4];
    #pragma unroll
    for (int i = 0; i < 4; i++)
        #pragma unroll
        for (int j = 0; j < 4; j++)
            #pragma unroll
            for (int c = 0; c < 4; c++) acc[i][j][c] = 0.0f;

    gemm128(smem, acc, wr, wc, g, t);
    __syncthreads();

    // T = relu(acc + b1) -> back into A (fp16); load W2
    #pragma unroll
    for (int i = 0; i < 4; i++) {
        #pragma unroll
        for (int j = 0; j < 4; j++) {
            int c0 = wc + j * 8 + 2 * t;
            int rA = wr + i * 16 + g;
            float bb0 = smf[SB1F + c0], bb1 = smf[SB1F + c0 + 1];
            float v00 = fmaxf(acc[i][j][0] + bb0, 0.0f);
            float v01 = fmaxf(acc[i][j][1] + bb1, 0.0f);
            float v10 = fmaxf(acc[i][j][2] + bb0, 0.0f);
            float v11 = fmaxf(acc[i][j][3] + bb1, 0.0f);
            __half2 p0 = __floats2half2_rn(v00, v01);
            __half2 p1 = __floats2half2_rn(v10, v11);
            *(uint32_t*)(smem + AH_B + (rA * 136 + c0) * 2) = *(uint32_t*)&p0;
            *(uint32_t*)(smem + AH_B + ((rA + 8) * 136 + c0) * 2) = *(uint32_t*)&p1;
            acc[i][j][0] = 0.0f; acc[i][j][1] = 0.0f;
            acc[i][j][2] = 0.0f; acc[i][j][3] = 0.0f;
        }
    }
    fill_w(smem, W2, wid, lane);
    __syncthreads();

    gemm128(smem, acc, wr, wc, g, t);
    __syncthreads();

    // stage z = acc + b2 into fp32 staging
    #pragma unroll
    for (int i = 0; i < 4; i++) {
        #pragma unroll
        for (int j = 0; j < 4; j++) {
            int c0 = wc + j * 8 + 2 * t;
            int rA = wr + i * 16 + g;
            float bb0 = smf[SB2F + c0], bb1 = smf[SB2F + c0 + 1];
            float2 u0 = make_float2(acc[i][j][0] + bb0, acc[i][j][1] + bb1);
            float2 u1 = make_float2(acc[i][j][2] + bb0, acc[i][j][3] + bb1);
            *(float2*)&smf[SZST + rA * 132 + c0] = u0;
            *(float2*)&smf[SZST + (rA + 8) * 132 + c0] = u1;
        }
    }
    __syncthreads();

    const int col4 = tid & 31;
    if (!last) {
        float s[4] = {0, 0, 0, 0}, q[4] = {0, 0, 0, 0};
        #pragma unroll
        for (int it = 0; it < 16; it++) {
            int row = (tid >> 5) + it * 8;
            int r = r0 + row;
            if (r < N_NODES) {
                float4 z4 = *(const float4*)&smf[SZST + row * 132 + col4 * 4];
                uint2 packed;
                packed.x = pack_h2(__float2half_rn(z4.x), __float2half_rn(z4.y));
                packed.y = pack_h2(__float2half_rn(z4.z), __float2half_rn(z4.w));
                *(uint2*)&g_h16[(size_t)r * D + col4 * 4] = packed;
                s[0] += z4.x; q[0] += z4.x * z4.x;
                s[1] += z4.y; q[1] += z4.y * z4.y;
                s[2] += z4.z; q[2] += z4.z * z4.z;
                s[3] += z4.w; q[3] += z4.w * z4.w;
            }
        }
        #pragma unroll
        for (int j = 0; j < 4; j++) {
            atomicAdd(&smf[SSUMF + col4 * 4 + j], s[j]);
            atomicAdd(&smf[SSQF + col4 * 4 + j], q[j]);
        }
        __syncthreads();
        if (tid < 128) {
            atomicAdd(&g_stats[layer * 2 * D + tid], smf[SSUMF + tid]);
            atomicAdd(&g_stats[layer * 2 * D + D + tid], smf[SSQF + tid]);
        }
    } else {
        int gcur = -1;
        float a0 = 0, a1 = 0, a2 = 0, a3 = 0;
        #pragma unroll 1
        for (int it = 0; it < 16; it++) {
            int row = (tid >> 5) + it * 8;
            int r = r0 + row;
            if (r < N_NODES) {
                float4 z4 = *(const float4*)&smf[SZST + row * 132 + col4 * 4];
                int gg = load_idx(batch, r);
                if (gg == gcur) {
                    a0 += z4.x; a1 += z4.y; a2 += z4.z; a3 += z4.w;
                } else {
                    if (gcur >= 0 && gcur < NUM_GRAPHS) {
                        atomicAdd(&out[gcur * D + col4 * 4 + 0], a0);
                        atomicAdd(&out[gcur * D + col4 * 4 + 1], a1);
                        atomicAdd(&out[gcur * D + col4 * 4 + 2], a2);
                        atomicAdd(&out[gcur * D + col4 * 4 + 3], a3);
                    }
                    gcur = gg; a0 = z4.x; a1 = z4.y; a2 = z4.z; a3 = z4.w;
                }
            }
        }
        if (gcur >= 0 && gcur < NUM_GRAPHS) {
            atomicAdd(&out[gcur * D + col4 * 4 + 0], a0);
            atomicAdd(&out[gcur * D + col4 * 4 + 1], a1);
            atomicAdd(&out[gcur * D + col4 * 4 + 2], a2);
            atomicAdd(&out[gcur * D + col4 * 4 + 3], a3);
        }
    }
}

// ---------------- launch ----------------
extern "C" void kernel_launch(void* const* d_in, const int* in_sizes, int n_in,
                              void* d_out, int out_size) {
    const float* x     = (const float*)d_in[0];
    const void*  ei    = d_in[1];
    const void*  batch = d_in[2];
    const float* W1    = (const float*)d_in[3];
    const float* b1    = (const float*)d_in[4];
    const float* W2    = (const float*)d_in[5];
    const float* b2    = (const float*)d_in[6];
    const float* eps   = (const float*)d_in[7];
    const float* gamma = (const float*)d_in[8];
    const float* beta  = (const float*)d_in[9];
    float* out = (float*)d_out;

    cudaFuncSetAttribute(gemm_mma, cudaFuncAttributeMaxDynamicSharedMemorySize,
                         SM_BYTES);

    zero_hist_kernel<<<(N_EDGES + 255) / 256, 256>>>(ei, x, out);   // 0
    scan_all_kernel<<<SCAN_NBLK, SCAN_BLK>>>();                     // 1
    fill_kernel<<<(N_EDGES + 255) / 256, 256>>>(ei);                // 2

    for (int i = 0; i < N_LAYERS; i++) {
        gather_kernel<<<(N_NODES + 7) / 8, 256>>>(                  // 3 on first iter
            eps, gamma + (i > 0 ? (i - 1) * D : 0),
            beta + (i > 0 ? (i - 1) * D : 0), i);
        gemm_mma<<<GEMM_GRID, 256, SM_BYTES>>>(
            W1 + i * D * D, b1 + i * D, W2 + i * D * D, b2 + i * D,
            i, out, batch, (i == N_LAYERS - 1) ? 1 : 0);
    }
}

// round 17
// speedup vs baseline: 1.1000x; 1.0185x over previous
#include <cuda_runtime.h>
#include <cuda_fp16.h>
#include <cstdint>

#define N_NODES 50000
#define N_EDGES 800000
#define D 128
#define NUM_GRAPHS 128
#define N_LAYERS 4
#define BN_EPS 1e-5f

#define MT 128
#define GEMM_GRID ((N_NODES + MT - 1) / MT)

#define SCAN_BLK 1024
#define SCAN_NBLK ((N_NODES + SCAN_BLK - 1) / SCAN_BLK)

// ---- smem byte map for gemm_mma (71680 B, 2 CTAs/SM) ----
#define AH_B 2048
#define WF_B (AH_B + 34816)
#define SM_BYTES (WF_B + 34816)   // 71680
#define SB1F  0
#define SB2F  128
#define SSUMF 256
#define SSQF  384
#define SZST  512                 // Z staging fp32 (spans A+W regions), stride 132

// ---------------- device scratch ----------------
__device__ __half g_h16[(size_t)N_NODES * D];
__device__ __half g_a16[(size_t)N_NODES * D];
__device__ int    g_deg[N_NODES];
__device__ int    g_ptr[N_NODES + 1];
__device__ int    g_cursor[N_NODES];
__device__ int    g_csr[N_EDGES];
__device__ int    g_bsum[SCAN_NBLK];
__device__ float  g_stats[(N_LAYERS - 1) * 2 * D];
__device__ int    g_idx64;
__device__ int    g_scan_done;

__device__ __forceinline__ int load_idx(const void* p, int i) {
    if (g_idx64) return (int)((const long long*)p)[i];
    return ((const int*)p)[i];
}

__device__ __forceinline__ uint32_t pack_h2(__half a, __half b) {
    __half2 h = __halves2half2(a, b);
    return *(uint32_t*)&h;
}

__device__ __forceinline__ uint32_t s2u(const void* p) {
    uint32_t a;
    asm("{ .reg .u64 t; cvta.to.shared.u64 t, %1; cvt.u32.u64 %0, t; }"
        : "=r"(a) : "l"(p));
    return a;
}

__device__ __forceinline__ void mma16(float* c, uint32_t a0, uint32_t a1,
                                      uint32_t a2, uint32_t a3,
                                      uint32_t b0, uint32_t b1) {
    asm volatile(
        "mma.sync.aligned.m16n8k16.row.col.f32.f16.f16.f32 "
        "{%0,%1,%2,%3}, {%4,%5,%6,%7}, {%8,%9}, {%0,%1,%2,%3};"
        : "+f"(c[0]), "+f"(c[1]), "+f"(c[2]), "+f"(c[3])
        : "r"(a0), "r"(a1), "r"(a2), "r"(a3), "r"(b0), "r"(b1));
}

__device__ __forceinline__ void ldsm_x4(uint32_t& r0, uint32_t& r1,
                                        uint32_t& r2, uint32_t& r3, uint32_t addr) {
    asm volatile("ldmatrix.sync.aligned.m8n8.x4.shared.b16 {%0,%1,%2,%3}, [%4];"
        : "=r"(r0), "=r"(r1), "=r"(r2), "=r"(r3) : "r"(addr));
}
__device__ __forceinline__ void ldsm_x2(uint32_t& r0, uint32_t& r1, uint32_t addr) {
    asm volatile("ldmatrix.sync.aligned.m8n8.x2.shared.b16 {%0,%1}, [%2];"
        : "=r"(r0), "=r"(r1) : "r"(addr));
}

// ---------------- launch 0: self-detect + hist + zero + x->fp16 ----------------
__global__ void zero_hist_kernel(const void* __restrict__ ei,
                                 const float* __restrict__ x,
                                 float* __restrict__ out) {
    __shared__ int snz;
    const int tid = threadIdx.x;
    if (tid == 0) snz = 0;
    __syncthreads();
    {
        int step = (2 * N_EDGES) / 256;
        int pos = (tid * step) | 1;
        if (((const int*)ei)[pos] != 0) snz = 1;
    }
    __syncthreads();
    const int idx64 = snz ? 0 : 1;

    int gidx = blockIdx.x * 256 + tid;
    if (gidx == 0) g_idx64 = idx64;

    if (gidx < N_EDGES) {
        int dst = idx64 ? (int)((const long long*)ei)[N_EDGES + gidx]
                        : ((const int*)ei)[N_EDGES + gidx];
        if (dst >= 0 && dst < N_NODES) atomicAdd(&g_deg[dst], 1);
    }

    int stride = gridDim.x * 256;
    for (int t = gidx; t < (N_LAYERS - 1) * 2 * D; t += stride) g_stats[t] = 0.0f;
    for (int t = gidx; t < NUM_GRAPHS * D; t += stride) out[t] = 0.0f;
    for (int t = gidx; t < N_NODES * (D / 2); t += stride) {
        float2 v = ((const float2*)x)[t];
        ((__half2*)g_h16)[t] = __floats2half2_rn(v.x, v.y);
    }
}

// ---------------- launch 1: full scan in one kernel ----------------
__global__ void scan_all_kernel() {
    __shared__ int wsum[32];
    __shared__ int sticket;
    const int tid = threadIdx.x;
    const int lane = tid & 31, wid = tid >> 5;
    int idx = blockIdx.x * SCAN_BLK + tid;
    int v = (idx < N_NODES) ? g_deg[idx] : 0;
    if (idx < N_NODES) g_deg[idx] = 0;
    int s = v;
    #pragma unroll
    for (int off = 1; off < 32; off <<= 1) {
        int t = __shfl_up_sync(0xffffffffu, s, off);
        if (lane >= off) s += t;
    }
    if (lane == 31) wsum[wid] = s;
    __syncthreads();
    if (wid == 0) {
        int ws = wsum[lane];
        #pragma unroll
        for (int off = 1; off < 32; off <<= 1) {
            int t = __shfl_up_sync(0xffffffffu, ws, off);
            if (lane >= off) ws += t;
        }
        wsum[lane] = ws;
    }
    __syncthreads();
    int incl = s + ((wid > 0) ? wsum[wid - 1] : 0);
    if (idx < N_NODES) g_ptr[idx + 1] = incl;
    if (tid == SCAN_BLK - 1) g_bsum[blockIdx.x] = incl;
    __threadfence();
    __syncthreads();
    if (tid == 0) sticket = atomicAdd(&g_scan_done, 1);
    __syncthreads();

    if (sticket == SCAN_NBLK - 1) {
        __shared__ int carry[SCAN_NBLK];
        if (tid < SCAN_NBLK) carry[tid] = ((volatile int*)g_bsum)[tid];
        __syncthreads();
        if (tid == 0) {
            int run = 0;
            for (int b = 0; b < SCAN_NBLK; b++) {
                int t = carry[b]; carry[b] = run; run += t;
            }
            g_scan_done = 0;
        }
        __syncthreads();
        volatile int* vptr = g_ptr;
        for (int i = tid; i < N_NODES; i += SCAN_BLK) {
            int p = vptr[i + 1] + carry[i / SCAN_BLK];
            g_ptr[i + 1] = p;
            if (i + 1 < N_NODES) g_cursor[i + 1] = p;
        }
        if (tid == 0) { g_ptr[0] = 0; g_cursor[0] = 0; }
    }
}

// ---------------- launch 2: CSR fill ----------------
__global__ void fill_kernel(const void* __restrict__ ei) {
    int e = blockIdx.x * blockDim.x + threadIdx.x;
    if (e >= N_EDGES) return;
    int src = load_idx(ei, e);
    int dst = load_idx(ei, N_EDGES + e);
    if (dst < 0 || dst >= N_NODES || src < 0 || src >= N_NODES) return;
    int p = atomicAdd(&g_cursor[dst], 1);
    if (p >= 0 && p < N_EDGES) g_csr[p] = src;
}

// ---------------- gather (fp16 src) + fused BN+ReLU via HFMA2_relu ----------------
__global__ void __launch_bounds__(256) gather_kernel(
    const float* __restrict__ eps_arr,
    const float* __restrict__ gamma, const float* __restrict__ beta,
    int layer)
{
    __shared__ float ssc[D], ssh[D];
    const int tid = threadIdx.x;
    const int apply_bn = (layer > 0);
    if (apply_bn && tid < D) {
        const float* stats = &g_stats[(layer - 1) * 2 * D];
        const float invN = 1.0f / (float)N_NODES;
        float mu = stats[tid] * invN;
        float var = stats[D + tid] * invN - mu * mu;
        float sc = rsqrtf(var + BN_EPS) * gamma[tid];
        ssc[tid] = sc;
        ssh[tid] = beta[tid] - mu * sc;
    }
    __syncthreads();

    const int lane = tid & 31, wid = tid >> 5;
    const int r = blockIdx.x * 8 + wid;
    if (r >= N_NODES) return;

    float4 sc4 = make_float4(1.f, 1.f, 1.f, 1.f);
    float4 sh4 = make_float4(0.f, 0.f, 0.f, 0.f);
    __half2 sc2a, sc2b, sh2a, sh2b;
    if (apply_bn) {
        sc4 = *(const float4*)&ssc[lane * 4];
        sh4 = *(const float4*)&ssh[lane * 4];
        sc2a = __floats2half2_rn(sc4.x, sc4.y);
        sc2b = __floats2half2_rn(sc4.z, sc4.w);
        sh2a = __floats2half2_rn(sh4.x, sh4.y);
        sh2b = __floats2half2_rn(sh4.z, sh4.w);
    }
    const float ep = 1.0f + eps_arr[layer];
    const uint2* __restrict__ h2p = (const uint2*)g_h16;

    float4 acc;
    {
        uint2 u = h2p[(size_t)r * 32 + lane];
        float2 f0 = __half22float2(*(__half2*)&u.x);
        float2 f1 = __half22float2(*(__half2*)&u.y);
        if (apply_bn) {
            acc.x = ep * fmaxf(f0.x * sc4.x + sh4.x, 0.0f);
            acc.y = ep * fmaxf(f0.y * sc4.y + sh4.y, 0.0f);
            acc.z = ep * fmaxf(f1.x * sc4.z + sh4.z, 0.0f);
            acc.w = ep * fmaxf(f1.y * sc4.w + sh4.w, 0.0f);
        } else {
            acc.x = ep * f0.x; acc.y = ep * f0.y;
            acc.z = ep * f1.x; acc.w = ep * f1.y;
        }
    }

    const int e0 = g_ptr[r], end = g_ptr[r + 1];
    if (apply_bn) {
        for (int base = e0; base < end; base += 32) {
            const int cnt = min(end - base, 32);
            int myidx = (lane < cnt) ? g_csr[base + lane] : 0;
            int t0 = 0;
            for (; t0 + 8 <= cnt; t0 += 8) {
                int ss[8];
                #pragma unroll
                for (int t = 0; t < 8; t++)
                    ss[t] = __shfl_sync(0xffffffffu, myidx, t0 + t);
                uint2 u[8];
                #pragma unroll
                for (int t = 0; t < 8; t++)
                    u[t] = h2p[(size_t)ss[t] * 32 + lane];
                #pragma unroll
                for (int t = 0; t < 8; t++) {
                    __half2 a0 = __hfma2_relu(*(__half2*)&u[t].x, sc2a, sh2a);
                    __half2 a1 = __hfma2_relu(*(__half2*)&u[t].y, sc2b, sh2b);
                    float2 f0 = __half22float2(a0);
                    float2 f1 = __half22float2(a1);
                    acc.x += f0.x; acc.y += f0.y;
                    acc.z += f1.x; acc.w += f1.y;
                }
            }
            for (; t0 < cnt; t0++) {
                int s = __shfl_sync(0xffffffffu, myidx, t0);
                uint2 u = h2p[(size_t)s * 32 + lane];
                __half2 a0 = __hfma2_relu(*(__half2*)&u.x, sc2a, sh2a);
                __half2 a1 = __hfma2_relu(*(__half2*)&u.y, sc2b, sh2b);
                float2 f0 = __half22float2(a0);
                float2 f1 = __half22float2(a1);
                acc.x += f0.x; acc.y += f0.y;
                acc.z += f1.x; acc.w += f1.y;
            }
        }
    } else {
        for (int base = e0; base < end; base += 32) {
            const int cnt = min(end - base, 32);
            int myidx = (lane < cnt) ? g_csr[base + lane] : 0;
            int t0 = 0;
            for (; t0 + 8 <= cnt; t0 += 8) {
                int ss[8];
                #pragma unroll
                for (int t = 0; t < 8; t++)
                    ss[t] = __shfl_sync(0xffffffffu, myidx, t0 + t);
                uint2 u[8];
                #pragma unroll
                for (int t = 0; t < 8; t++)
                    u[t] = h2p[(size_t)ss[t] * 32 + lane];
                #pragma unroll
                for (int t = 0; t < 8; t++) {
                    float2 f0 = __half22float2(*(__half2*)&u[t].x);
                    float2 f1 = __half22float2(*(__half2*)&u[t].y);
                    acc.x += f0.x; acc.y += f0.y;
                    acc.z += f1.x; acc.w += f1.y;
                }
            }
            for (; t0 < cnt; t0++) {
                int s = __shfl_sync(0xffffffffu, myidx, t0);
                uint2 u = h2p[(size_t)s * 32 + lane];
                float2 f0 = __half22float2(*(__half2*)&u.x);
                float2 f1 = __half22float2(*(__half2*)&u.y);
                acc.x += f0.x; acc.y += f0.y;
                acc.z += f1.x; acc.w += f1.y;
            }
        }
    }
    uint2 packed;
    packed.x = pack_h2(__float2half_rn(acc.x), __float2half_rn(acc.y));
    packed.y = pack_h2(__float2half_rn(acc.z), __float2half_rn(acc.w));
    ((uint2*)g_a16)[(size_t)r * 32 + lane] = packed;
}

// ---------------- W fill: global [k][n] fp32 -> smem [n][k] fp16 ----------------
__device__ __forceinline__ void fill_w(char* smem, const float* __restrict__ Wg,
                                       int wid, int lane) {
    #pragma unroll 1
    for (int s = 0; s < 8; s++) {
        int task = wid + s * 8;
        int k0 = (task >> 2) * 8;
        int n = (task & 3) * 32 + lane;
        float w[8];
        #pragma unroll
        for (int r = 0; r < 8; r++) w[r] = Wg[(size_t)(k0 + r) * 128 + n];
        __half hh[8];
        #pragma unroll
        for (int r = 0; r < 8; r++) hh[r] = __float2half_rn(w[r]);
        uint4 uh;
        uh.x = pack_h2(hh[0], hh[1]); uh.y = pack_h2(hh[2], hh[3]);
        uh.z = pack_h2(hh[4], hh[5]); uh.w = pack_h2(hh[6], hh[7]);
        *(uint4*)(smem + WF_B + ((size_t)n * 136 + k0) * 2) = uh;
    }
}

// ---------------- one 128x128x128 GEMM via ldmatrix (A fp16, W fp16) ------------
__device__ __forceinline__ void gemm128(uint32_t a_base, uint32_t w_base,
                                        float (&acc)[4][4][4])
{
    #pragma unroll 1
    for (int ks = 0; ks < 8; ks++) {
        uint32_t ah[4][4];
        #pragma unroll
        for (int i = 0; i < 4; i++)
            ldsm_x4(ah[i][0], ah[i][1], ah[i][2], ah[i][3],
                    a_base + i * 4352 + ks * 32);
        #pragma unroll
        for (int j = 0; j < 4; j++) {
            uint32_t b0, b1;
            ldsm_x2(b0, b1, w_base + j * 2176 + ks * 32);
            #pragma unroll
            for (int i = 0; i < 4; i++)
                mma16(acc[i][j], ah[i][0], ah[i][1], ah[i][2], ah[i][3], b0, b1);
        }
    }
}

// ---------------- GEMM kernel: Z = relu(A@W1+b1)@W2 + b2 + epilogue ----------------
__global__ void __launch_bounds__(256, 2) gemm_mma(
    const float* __restrict__ W1, const float* __restrict__ b1,
    const float* __restrict__ W2, const float* __restrict__ b2,
    int layer, float* __restrict__ out, const void* __restrict__ batch, int last)
{
    extern __shared__ char smem[];
    float* smf = (float*)smem;
    const uint32_t su = s2u(smem);
    const int tid = threadIdx.x;
    const int wid = tid >> 5, lane = tid & 31;
    const int g = lane >> 2, t = lane & 3;
    const int wr = (wid >> 2) * 64;
    const int wc = (wid & 3) * 32;
    const int r0 = blockIdx.x * MT;

    // ldmatrix per-lane base addresses
    const uint32_t a_base = su + AH_B
        + (uint32_t)(wr + (lane & 7) + ((lane >> 3) & 1) * 8) * 272
        + ((lane >> 4) & 1) * 16;
    const uint32_t w_base = su + WF_B
        + (uint32_t)(wc + (lane & 7)) * 272
        + ((lane >> 3) & 1) * 16;

    if (tid < 128) {
        smf[SB1F + tid] = b1[tid];
        smf[SB2F + tid] = b2[tid];
        smf[SSUMF + tid] = 0.0f;
        smf[SSQF + tid] = 0.0f;
    }

    // A fill: fp16 g_a16 -> smem, straight uint4 copies
    #pragma unroll
    for (int it = 0; it < 8; it++) {
        int idx = tid + it * 256;
        int m = idx >> 4, c8 = idx & 15;
        uint4 v = make_uint4(0u, 0u, 0u, 0u);
        if (r0 + m < N_NODES) v = ((const uint4*)g_a16)[(size_t)(r0 + m) * 16 + c8];
        *(uint4*)(smem + AH_B + ((size_t)m * 136 + c8 * 8) * 2) = v;
    }
    fill_w(smem, W1, wid, lane);
    __syncthreads();

    float acc[4][4][4];
    #pragma unroll
    for (int i = 0; i < 4; i++)
        #pragma unroll
        for (int j = 0; j < 4; j++)
            #pragma unroll
            for (int c = 0; c < 4; c++) acc[i][j][c] = 0.0f;

    gemm128(a_base, w_base, acc);
    __syncthreads();

    // T = relu(acc + b1) -> back into A (fp16); load W2
    #pragma unroll
    for (int i = 0; i < 4; i++) {
        #pragma unroll
        for (int j = 0; j < 4; j++) {
            int c0 = wc + j * 8 + 2 * t;
            int rA = wr + i * 16 + g;
            float bb0 = smf[SB1F + c0], bb1 = smf[SB1F + c0 + 1];
            float v00 = fmaxf(acc[i][j][0] + bb0, 0.0f);
            float v01 = fmaxf(acc[i][j][1] + bb1, 0.0f);
            float v10 = fmaxf(acc[i][j][2] + bb0, 0.0f);
            float v11 = fmaxf(acc[i][j][3] + bb1, 0.0f);
            __half2 p0 = __floats2half2_rn(v00, v01);
            __half2 p1 = __floats2half2_rn(v10, v11);
            *(uint32_t*)(smem + AH_B + (rA * 136 + c0) * 2) = *(uint32_t*)&p0;
            *(uint32_t*)(smem + AH_B + ((rA + 8) * 136 + c0) * 2) = *(uint32_t*)&p1;
            acc[i][j][0] = 0.0f; acc[i][j][1] = 0.0f;
            acc[i][j][2] = 0.0f; acc[i][j][3] = 0.0f;
        }
    }
    fill_w(smem, W2, wid, lane);
    __syncthreads();

    gemm128(a_base, w_base, acc);
    __syncthreads();

    // stage z = acc + b2 into fp32 staging
    #pragma unroll
    for (int i = 0; i < 4; i++) {
        #pragma unroll
        for (int j = 0; j < 4; j++) {
            int c0 = wc + j * 8 + 2 * t;
            int rA = wr + i * 16 + g;
            float bb0 = smf[SB2F + c0], bb1 = smf[SB2F + c0 + 1];
            float2 u0 = make_float2(acc[i][j][0] + bb0, acc[i][j][1] + bb1);
            float2 u1 = make_float2(acc[i][j][2] + bb0, acc[i][j][3] + bb1);
            *(float2*)&smf[SZST + rA * 132 + c0] = u0;
            *(float2*)&smf[SZST + (rA + 8) * 132 + c0] = u1;
        }
    }
    __syncthreads();

    const int col4 = tid & 31;
    if (!last) {
        float s[4] = {0, 0, 0, 0}, q[4] = {0, 0, 0, 0};
        #pragma unroll
        for (int it = 0; it < 16; it++) {
            int row = (tid >> 5) + it * 8;
            int r = r0 + row;
            if (r < N_NODES) {
                float4 z4 = *(const float4*)&smf[SZST + row * 132 + col4 * 4];
                uint2 packed;
                packed.x = pack_h2(__float2half_rn(z4.x), __float2half_rn(z4.y));
                packed.y = pack_h2(__float2half_rn(z4.z), __float2half_rn(z4.w));
                *(uint2*)&g_h16[(size_t)r * D + col4 * 4] = packed;
                s[0] += z4.x; q[0] += z4.x * z4.x;
                s[1] += z4.y; q[1] += z4.y * z4.y;
                s[2] += z4.z; q[2] += z4.z * z4.z;
                s[3] += z4.w; q[3] += z4.w * z4.w;
            }
        }
        #pragma unroll
        for (int j = 0; j < 4; j++) {
            atomicAdd(&smf[SSUMF + col4 * 4 + j], s[j]);
            atomicAdd(&smf[SSQF + col4 * 4 + j], q[j]);
        }
        __syncthreads();
        if (tid < 128) {
            atomicAdd(&g_stats[layer * 2 * D + tid], smf[SSUMF + tid]);
            atomicAdd(&g_stats[layer * 2 * D + D + tid], smf[SSQF + tid]);
        }
    } else {
        int gcur = -1;
        float a0 = 0, a1 = 0, a2 = 0, a3 = 0;
        #pragma unroll 1
        for (int it = 0; it < 16; it++) {
            int row = (tid >> 5) + it * 8;
            int r = r0 + row;
            if (r < N_NODES) {
                float4 z4 = *(const float4*)&smf[SZST + row * 132 + col4 * 4];
                int gg = load_idx(batch, r);
                if (gg == gcur) {
                    a0 += z4.x; a1 += z4.y; a2 += z4.z; a3 += z4.w;
                } else {
                    if (gcur >= 0 && gcur < NUM_GRAPHS) {
                        atomicAdd(&out[gcur * D + col4 * 4 + 0], a0);
                        atomicAdd(&out[gcur * D + col4 * 4 + 1], a1);
                        atomicAdd(&out[gcur * D + col4 * 4 + 2], a2);
                        atomicAdd(&out[gcur * D + col4 * 4 + 3], a3);
                    }
                    gcur = gg; a0 = z4.x; a1 = z4.y; a2 = z4.z; a3 = z4.w;
                }
            }
        }
        if (gcur >= 0 && gcur < NUM_GRAPHS) {
            atomicAdd(&out[gcur * D + col4 * 4 + 0], a0);
            atomicAdd(&out[gcur * D + col4 * 4 + 1], a1);
            atomicAdd(&out[gcur * D + col4 * 4 + 2], a2);
            atomicAdd(&out[gcur * D + col4 * 4 + 3], a3);
        }
    }
}

// ---------------- launch ----------------
extern "C" void kernel_launch(void* const* d_in, const int* in_sizes, int n_in,
                              void* d_out, int out_size) {
    const float* x     = (const float*)d_in[0];
    const void*  ei    = d_in[1];
    const void*  batch = d_in[2];
    const float* W1    = (const float*)d_in[3];
    const float* b1    = (const float*)d_in[4];
    const float* W2    = (const float*)d_in[5];
    const float* b2    = (const float*)d_in[6];
    const float* eps   = (const float*)d_in[7];
    const float* gamma = (const float*)d_in[8];
    const float* beta  = (const float*)d_in[9];
    float* out = (float*)d_out;

    cudaFuncSetAttribute(gemm_mma, cudaFuncAttributeMaxDynamicSharedMemorySize,
                         SM_BYTES);

    zero_hist_kernel<<<(N_EDGES + 255) / 256, 256>>>(ei, x, out);   // 0
    scan_all_kernel<<<SCAN_NBLK, SCAN_BLK>>>();                     // 1
    fill_kernel<<<(N_EDGES + 255) / 256, 256>>>(ei);                // 2

    for (int i = 0; i < N_LAYERS; i++) {
        gather_kernel<<<(N_NODES + 7) / 8, 256>>>(                  // 3 on first iter
            eps, gamma + (i > 0 ? (i - 1) * D : 0),
            beta + (i > 0 ? (i - 1) * D : 0), i);
        gemm_mma<<<GEMM_GRID, 256, SM_BYTES>>>(
            W1 + i * D * D, b1 + i * D, W2 + i * D * D, b2 + i * D,
            i, out, batch, (i == N_LAYERS - 1) ? 1 : 0);
    }
}